// round 6
// baseline (speedup 1.0000x reference)
#include <cuda_runtime.h>

// Shape (fixed by reference)
#define B_     16
#define T_     4096
#define D_     512
#define L_     64                 // t-steps per block tile
#define Q_     16                 // t-steps per rescan quarter
#define DG_    128                // d-lanes per block
#define NDG    (D_ / DG_)         // 4
#define C_     (T_ / L_)          // 64 chunks per chain
#define NCHAIN (B_ * NDG)         // 64 chains
#define NBLK   (NCHAIN * C_)      // 4096 blocks
#define THREADS 256

// Decoupled-lookback state (static __device__ scratch; flags re-zeroed per launch)
__device__ float2 g_agg [(size_t)NBLK * DG_];   // local aggregates   (4 MB)
__device__ float2 g_incl[(size_t)NBLK * DG_];   // inclusive prefixes (4 MB)
__device__ int    g_flag[NBLK];                 // 0=none, 1=agg, 2=inclusive

// ---------------------------------------------------------------------------
// Warp-specialized decoupled-lookback scan.
//   bid = c*NCHAIN + chain (waves span all chains -> shallow lookback).
//   Phase 1 (concurrent):
//     h1 (warps 4-7): tile load -> 64-step scan from zero, snapshotting the
//        state at t=16/32/48 -> publish aggregate.
//     h0 (warps 0-3): lookback -> block carry -> sqin[0].
//   Phase 2 (concurrent): h0 publishes inclusive; h1 builds quarter-entry
//     states sqin[1..3][d] = A^{16k}*carry + S_k.
//   Phase 3 (all 256): 4 t-quarters x 64 lanes x 2 d-lanes; 16-step rescan,
//     float4 stores (2 complex outputs per STG.128).
// ---------------------------------------------------------------------------
__global__ void __launch_bounds__(THREADS, 6) scan_kernel(
    const float* __restrict__ x,
    const float* __restrict__ Ar,
    const float* __restrict__ Ai,
    float2* __restrict__ out)
{
    __shared__ float  sx[L_ * DG_];      // 32 KB x tile, [t][d]
    __shared__ float2 sqin[4][DG_];      // quarter-entry states (sqin[0]=carry)
    __shared__ float2 sagg[DG_];         // block aggregate (h1 -> h0)

    const int tid   = threadIdx.x;
    const int bid   = blockIdx.x;
    const int chain = bid & (NCHAIN - 1);
    const int c     = bid >> 6;                 // / NCHAIN
    const int dg    = chain & (NDG - 1);
    const int b     = chain >> 2;               // / NDG
    const int h     = tid >> 7;                 // 0: lookback, 1: scan

    if (h == 1) {
        // ===== h1: tile load + 64-step scan with snapshots + agg publish =====
        const int d = tid - 128;
        const float ar = Ar[dg * DG_ + d];
        const float ai = Ai[dg * DG_ + d];

        const float* xb = x + ((size_t)b * T_ + (size_t)c * L_) * D_ + dg * DG_;
        {
            const int lane4 = d & 31;           // float4 column (32 per row)
            const int rsub  = d >> 5;           // 0..3
            float4* s4 = (float4*)sx;
            #pragma unroll
            for (int r = 0; r < L_ / 4; ++r) {
                const int row = r * 4 + rsub;
                s4[row * (DG_ / 4) + lane4] =
                    __ldcs((const float4*)(xb + (size_t)row * D_) + lane4);
            }
        }
        asm volatile("bar.sync 1, 128;" ::: "memory");   // tile ready (h1)

        const float* sxd = sx + d;
        float er = 0.0f, ei = 0.0f;
        float s16r, s16i, s32r, s32i, s48r, s48i;
        #pragma unroll
        for (int t = 0; t < L_; ++t) {
            const float xv = sxd[t * DG_];
            const float nr = fmaf(er, ar, fmaf(-ei, ai, xv));
            const float ni = fmaf(er, ai, ei * ar);
            er = nr; ei = ni;
            if (t == Q_ - 1)     { s16r = er; s16i = ei; }
            if (t == 2*Q_ - 1)   { s32r = er; s32i = ei; }
            if (t == 3*Q_ - 1)   { s48r = er; s48i = ei; }
        }
        sagg[d] = make_float2(er, ei);           // block aggregate (from zero)

        if (c == 0) {
            g_incl[(size_t)bid * DG_ + d] = make_float2(er, ei);
        } else if (c < C_ - 1) {
            g_agg[(size_t)bid * DG_ + d] = make_float2(er, ei);
        }
        __threadfence();
        asm volatile("bar.sync 1, 128;" ::: "memory");
        if (tid == 128 && c < C_ - 1) atomicExch(&g_flag[bid], c == 0 ? 2 : 1);

        __syncthreads();   // join: carry (sqin[0]) valid

        // ---- phase 2: quarter-entry states from carry + snapshots ----------
        const float2 cv = sqin[0][d];
        float p16r = ar, p16i = ai;
        #pragma unroll
        for (int k = 0; k < 4; ++k) {            // A^16
            const float nr = p16r * p16r - p16i * p16i;
            const float ni = 2.0f * p16r * p16i;
            p16r = nr; p16i = ni;
        }
        const float p32r = p16r * p16r - p16i * p16i;
        const float p32i = 2.0f * p16r * p16i;
        const float p48r = p32r * p16r - p32i * p16i;
        const float p48i = p32r * p16i + p32i * p16r;

        sqin[1][d] = make_float2(fmaf(p16r, cv.x, fmaf(-p16i, cv.y, s16r)),
                                 fmaf(p16i, cv.x, fmaf( p16r, cv.y, s16i)));
        sqin[2][d] = make_float2(fmaf(p32r, cv.x, fmaf(-p32i, cv.y, s32r)),
                                 fmaf(p32i, cv.x, fmaf( p32r, cv.y, s32i)));
        sqin[3][d] = make_float2(fmaf(p48r, cv.x, fmaf(-p48i, cv.y, s48r)),
                                 fmaf(p48i, cv.x, fmaf( p48r, cv.y, s48i)));
    } else {
        // ===== h0: lookback concurrent with h1's scan ========================
        const int d = tid;
        const float ar = Ar[dg * DG_ + d];
        const float ai = Ai[dg * DG_ + d];
        float p64r = ar, p64i = ai;
        #pragma unroll
        for (int k = 0; k < 6; ++k) {            // A^64
            const float nr = p64r * p64r - p64i * p64i;
            const float ni = 2.0f * p64r * p64i;
            p64r = nr; p64i = ni;
        }

        float cr = 0.0f, ci = 0.0f;
        if (c > 0) {
            float mr = 1.0f, mi = 0.0f;          // running multiplier A^(64k)
            int j = bid - NCHAIN;                // predecessor, same chain
            while (true) {
                volatile int* f = &g_flag[j];
                int v = *f;
                while (v == 0) { __nanosleep(40); v = *f; }
                __threadfence();                 // acquire
                const float2 val = (v == 2)
                    ? __ldcg(&g_incl[(size_t)j * DG_ + d])
                    : __ldcg(&g_agg [(size_t)j * DG_ + d]);
                cr = fmaf(mr, val.x, fmaf(-mi, val.y, cr));
                ci = fmaf(mi, val.x, fmaf( mr, val.y, ci));
                if (v == 2) break;               // prefix complete
                const float nmr = mr * p64r - mi * p64i;
                const float nmi = mr * p64i + mi * p64r;
                mr = nmr; mi = nmi;
                j -= NCHAIN;
            }
        }
        sqin[0][d] = make_float2(cr, ci);

        __syncthreads();   // join: sagg valid

        // ---- phase 2: publish inclusive = A^64*carry + agg ------------------
        if (c > 0 && c < C_ - 1) {
            const float2 ag = sagg[d];
            const float inr = fmaf(p64r, cr, fmaf(-p64i, ci, ag.x));
            const float ini = fmaf(p64i, cr, fmaf( p64r, ci, ag.y));
            g_incl[(size_t)bid * DG_ + d] = make_float2(inr, ini);
            __threadfence();
            asm volatile("bar.sync 2, 128;" ::: "memory");
            if (tid == 0) atomicExch(&g_flag[bid], 2);
        }
    }

    __syncthreads();   // sqin[0..3] valid for everyone

    // ===== phase 3: 4 quarters x 64 lanes x 2 d-lanes, float4 stores =========
    {
        const int q    = tid >> 6;               // 0..3
        const int lane = tid & 63;
        const int d0   = 2 * lane;
        const int dglb = dg * DG_ + d0;

        const float ar0 = Ar[dglb],     ai0 = Ai[dglb];
        const float ar1 = Ar[dglb + 1], ai1 = Ai[dglb + 1];

        const float4 e = ((const float4*)sqin[q])[lane];   // (r0,i0,r1,i1)
        float r0 = e.x, i0 = e.y, r1 = e.z, i1 = e.w;

        const float2* sx2 = (const float2*)sx + (size_t)q * Q_ * (DG_ / 2) + lane;
        float4* ob = (float4*)(out + ((size_t)b * T_ + (size_t)c * L_ + q * Q_) * D_ + dglb);

        #pragma unroll
        for (int t = 0; t < Q_; ++t) {
            const float2 xv = sx2[t * (DG_ / 2)];
            const float nr0 = fmaf(r0, ar0, fmaf(-i0, ai0, xv.x));
            const float ni0 = fmaf(r0, ai0, i0 * ar0);
            const float nr1 = fmaf(r1, ar1, fmaf(-i1, ai1, xv.y));
            const float ni1 = fmaf(r1, ai1, i1 * ar1);
            r0 = nr0; i0 = ni0; r1 = nr1; i1 = ni1;
            __stcs(&ob[(size_t)t * (D_ / 2)], make_float4(nr0, ni0, nr1, ni1));
        }
    }
}

// ---------------------------------------------------------------------------
// Inputs (metadata order): x [B*T*D] f32, A_real [D] f32, A_imag [D] f32.
// Output: [B, T, D, 2] f32.
// ---------------------------------------------------------------------------
extern "C" void kernel_launch(void* const* d_in, const int* in_sizes, int n_in,
                              void* d_out, int out_size)
{
    const float* x  = (const float*)d_in[0];
    const float* Ar = (const float*)d_in[1];
    const float* Ai = (const float*)d_in[2];
    float2* out = (float2*)d_out;

    static void* flag_ptr = nullptr;
    if (!flag_ptr) cudaGetSymbolAddress(&flag_ptr, g_flag);

    cudaMemsetAsync(flag_ptr, 0, NBLK * sizeof(int));   // graph-capturable memset node
    scan_kernel<<<NBLK, THREADS>>>(x, Ar, Ai, out);
}